// round 4
// baseline (speedup 1.0000x reference)
#include <cuda_runtime.h>

// Problem constants
#define BB 256
#define TT 4096
#define HH 64
#define TPB 256
#define CHUNKS (TT / TPB)          // 16
#define NBLOCKS (BB * CHUNKS)      // 4096

// Deterministic reduction scratch (no atomics, no allocation)
__device__ float g_partial[NBLOCKS];

__global__ __launch_bounds__(TPB) void pinn_point_kernel(
    const float* __restrict__ t,
    const float* __restrict__ x_target,
    const float* __restrict__ params_pred,
    const float* __restrict__ W1,
    const float* __restrict__ b1,
    const float* __restrict__ W2,
    const float* __restrict__ b2)
{
    __shared__ float4 sW2[HH * 4];   // 64 rows x 16 cols, row-major, as float4
    __shared__ float sW1[HH];
    __shared__ float sB1[HH];
    __shared__ float sB2[16];
    __shared__ float sP[144];        // [0:8)=g [8:16)=mu [16:80)=Pi [80:144)=Gamma

    const int b     = blockIdx.x >> 4;            // / CHUNKS
    const int chunk = blockIdx.x & (CHUNKS - 1);
    const int tid   = threadIdx.x;

    // Stage weights + per-batch params into shared
    {
        const float4* w2v = (const float4*)W2;
        sW2[tid] = w2v[tid];                      // HH*4 == TPB == 256
    }
    if (tid < HH) { sW1[tid] = W1[tid]; sB1[tid] = b1[tid]; }
    else if (tid < HH + 16) { sB2[tid - HH] = b2[tid - HH]; }
    if (tid >= 112) { sP[tid - 112] = params_pred[b * 144 + (tid - 112)]; }
    __syncthreads();

    const int   ti = chunk * TPB + tid;
    const float tv = t[b * TT + ti];

    // Two fused 64->16 contractions: latent (h@W2) and dlatent (((1-h^2)*W1)@W2)
    float lat[16], dlat[16];
    #pragma unroll
    for (int j = 0; j < 16; ++j) { lat[j] = 0.f; dlat[j] = 0.f; }

    #pragma unroll 4
    for (int k = 0; k < HH; ++k) {
        const float h  = tanhf(fmaf(tv, sW1[k], sB1[k]));
        const float hp = (1.0f - h * h) * sW1[k];
        #pragma unroll
        for (int jj = 0; jj < 4; ++jj) {
            const float4 w = sW2[k * 4 + jj];
            lat [4*jj+0] = fmaf(h,  w.x, lat [4*jj+0]);
            lat [4*jj+1] = fmaf(h,  w.y, lat [4*jj+1]);
            lat [4*jj+2] = fmaf(h,  w.z, lat [4*jj+2]);
            lat [4*jj+3] = fmaf(h,  w.w, lat [4*jj+3]);
            dlat[4*jj+0] = fmaf(hp, w.x, dlat[4*jj+0]);
            dlat[4*jj+1] = fmaf(hp, w.y, dlat[4*jj+1]);
            dlat[4*jj+2] = fmaf(hp, w.z, dlat[4*jj+2]);
            dlat[4*jj+3] = fmaf(hp, w.w, dlat[4*jj+3]);
        }
    }

    // Observables + JVP through relu gate
    float st[16], ds[16];
    #pragma unroll
    for (int j = 0; j < 8; ++j) {
        st[j] = lat[j] + sB2[j];
        ds[j] = dlat[j];
    }
    #pragma unroll
    for (int j = 0; j < 8; ++j) {
        const float q   = lat[8 + j] + sB2[8 + j];
        const float r   = q - sP[8 + j];          // q - mu
        const bool  pos = (r > 0.0f);             // JAX relu jvp: x>0 passes tangent
        st[8 + j] = pos ? r : 0.0f;
        ds[8 + j] = pos ? dlat[8 + j] : 0.0f;
    }

    // Data loss terms
    float err = 0.0f;
    #pragma unroll
    for (int j = 0; j < 16; ++j) {
        const float d = st[j] - x_target[(size_t)(b * 16 + j) * TT + ti];
        err = fmaf(d, d, err);
    }

    // Physics loss terms: da = g + Pi@x - a ; dx = (Gamma@a) * (mu - x)
    #pragma unroll
    for (int i = 0; i < 8; ++i) {
        float acc = sP[i];                        // g[i]
        #pragma unroll
        for (int j = 0; j < 8; ++j)
            acc = fmaf(sP[16 + i * 8 + j], st[8 + j], acc);   // Pi@x
        const float da = acc - st[i];
        const float d1 = ds[i] - da;
        err = fmaf(d1, d1, err);

        float ga = 0.0f;
        #pragma unroll
        for (int j = 0; j < 8; ++j)
            ga = fmaf(sP[80 + i * 8 + j], st[j], ga);         // Gamma@a
        const float dx = ga * (sP[8 + i] - st[8 + i]);        // * (mu - x)
        const float d2 = ds[8 + i] - dx;
        err = fmaf(d2, d2, err);
    }

    // Block reduction (deterministic)
    #pragma unroll
    for (int off = 16; off; off >>= 1)
        err += __shfl_xor_sync(0xffffffffu, err, off);
    __shared__ float sred[TPB / 32];
    if ((tid & 31) == 0) sred[tid >> 5] = err;
    __syncthreads();
    if (tid == 0) {
        float s = 0.0f;
        #pragma unroll
        for (int w = 0; w < TPB / 32; ++w) s += sred[w];
        g_partial[blockIdx.x] = s;
    }
}

__global__ __launch_bounds__(256) void pinn_finalize(
    const float* __restrict__ params_pred,
    const float* __restrict__ params_target,
    const float* __restrict__ ic_pred,
    const float* __restrict__ ic_target,
    float* __restrict__ out)
{
    const int tid = threadIdx.x;

    // Sum point-kernel partials (data + physics sums of squares)
    float s = 0.0f;
    for (int i = tid; i < NBLOCKS; i += 256) s += g_partial[i];

    // Supervised loss: concat(params, ic) vs targets
    float sup = 0.0f;
    for (int i = tid; i < BB * 144; i += 256) {
        const float d = params_pred[i] - params_target[i];
        sup = fmaf(d, d, sup);
    }
    for (int i = tid; i < BB * 16; i += 256) {
        const float d = ic_pred[i] - ic_target[i];
        sup = fmaf(d, d, sup);
    }

    #pragma unroll
    for (int off = 16; off; off >>= 1) {
        s   += __shfl_xor_sync(0xffffffffu, s,   off);
        sup += __shfl_xor_sync(0xffffffffu, sup, off);
    }
    __shared__ float r1[8], r2[8];
    if ((tid & 31) == 0) { r1[tid >> 5] = s; r2[tid >> 5] = sup; }
    __syncthreads();
    if (tid == 0) {
        float a = 0.0f, c = 0.0f;
        #pragma unroll
        for (int w = 0; w < 8; ++w) { a += r1[w]; c += r2[w]; }
        // data+physics both divide by B*T*2N = 256*4096*16 = 16777216
        out[0] = a * (1.0f / 16777216.0f) + c * (1.0f / 40960.0f);
    }
}

extern "C" void kernel_launch(void* const* d_in, const int* in_sizes, int n_in,
                              void* d_out, int out_size) {
    const float* t             = (const float*)d_in[0];
    const float* x_target      = (const float*)d_in[1];
    const float* params_pred   = (const float*)d_in[2];
    const float* params_target = (const float*)d_in[3];
    const float* ic_pred       = (const float*)d_in[4];
    const float* ic_target     = (const float*)d_in[5];
    const float* W1            = (const float*)d_in[6];
    const float* b1            = (const float*)d_in[7];
    const float* W2            = (const float*)d_in[8];
    const float* b2            = (const float*)d_in[9];

    pinn_point_kernel<<<NBLOCKS, TPB>>>(t, x_target, params_pred, W1, b1, W2, b2);
    pinn_finalize<<<1, 256>>>(params_pred, params_target, ic_pred, ic_target, (float*)d_out);
}

// round 5
// speedup vs baseline: 1.1263x; 1.1263x over previous
#include <cuda_runtime.h>

// Problem constants
#define BB 256
#define TT 4096
#define HH 64
#define TPB 256
#define PTS 512                     // points per block (2 per thread)
#define CHUNKS (TT / PTS)           // 8
#define NBLOCKS (BB * CHUNKS)       // 2048

typedef unsigned long long ull;

// Deterministic reduction scratch (no atomics, no allocation)
__device__ float g_partial[NBLOCKS];

__device__ __forceinline__ ull pack2(float lo, float hi) {
    ull r; asm("mov.b64 %0, {%1, %2};" : "=l"(r) : "f"(lo), "f"(hi)); return r;
}
__device__ __forceinline__ void unpack2(ull v, float& lo, float& hi) {
    asm("mov.b64 {%0, %1}, %2;" : "=f"(lo), "=f"(hi) : "l"(v));
}
// packed 2x fp32 FMA (FFMA2) — PTX-only on sm_103a
__device__ __forceinline__ ull fma2(ull a, ull b, ull c) {
    ull d; asm("fma.rn.f32x2 %0, %1, %2, %3;" : "=l"(d) : "l"(a), "l"(b), "l"(c)); return d;
}
// hardware tanh (MUFU.TANH)
__device__ __forceinline__ float tanh_fast(float x) {
    float y; asm("tanh.approx.f32 %0, %1;" : "=f"(y) : "f"(x)); return y;
}

__global__ __launch_bounds__(TPB, 2) void pinn_point_kernel(
    const float* __restrict__ t,
    const float* __restrict__ x_target,
    const float* __restrict__ params_pred,
    const float* __restrict__ params_target,
    const float* __restrict__ ic_pred,
    const float* __restrict__ ic_target,
    const float* __restrict__ W1,
    const float* __restrict__ b1,
    const float* __restrict__ W2,
    const float* __restrict__ b2)
{
    // W2 duplicated as packed pairs: entry (k,e) = {(w[k][2e],w[k][2e]), (w[k][2e+1],w[k][2e+1])}
    __shared__ ulonglong2 sW2d[HH * 8];
    __shared__ float sW1[HH];
    __shared__ float sB1[HH];
    __shared__ float sB2[16];
    __shared__ float sP[144];        // [0:8)=g [8:16)=mu [16:80)=Pi [80:144)=Gamma

    const int b     = blockIdx.x >> 3;            // / CHUNKS
    const int chunk = blockIdx.x & (CHUNKS - 1);
    const int tid   = threadIdx.x;

    // Stage weights (duplicated-packed) + per-batch params into shared
    #pragma unroll
    for (int idx = tid; idx < HH * 8; idx += TPB) {
        const int k = idx >> 3, e = idx & 7;
        const float w0 = W2[k * 16 + 2 * e];
        const float w1 = W2[k * 16 + 2 * e + 1];
        ulonglong2 u; u.x = pack2(w0, w0); u.y = pack2(w1, w1);
        sW2d[idx] = u;
    }
    if (tid < HH) { sW1[tid] = W1[tid]; sB1[tid] = b1[tid]; }
    else if (tid < HH + 16) { sB2[tid - HH] = b2[tid - HH]; }
    if (tid >= 112) { sP[tid - 112] = params_pred[b * 144 + (tid - 112)]; }
    __syncthreads();

    const int   base = chunk * PTS + tid;
    const float t0 = t[b * TT + base];
    const float t1 = t[b * TT + base + 256];

    // Packed accumulators: lane0 = point ti, lane1 = point ti+256
    ull lat2[16], dlat2[16];
    #pragma unroll
    for (int j = 0; j < 16; ++j) { lat2[j] = 0ull; dlat2[j] = 0ull; }

    #pragma unroll 4
    for (int k = 0; k < HH; ++k) {
        const float w1k = sW1[k], b1k = sB1[k];
        const float h0 = tanh_fast(fmaf(t0, w1k, b1k));
        const float h1 = tanh_fast(fmaf(t1, w1k, b1k));
        const float hp0 = fmaf(-h0, h0, 1.0f) * w1k;
        const float hp1 = fmaf(-h1, h1, 1.0f) * w1k;
        const ull hh = pack2(h0, h1);
        const ull hp = pack2(hp0, hp1);
        #pragma unroll
        for (int e = 0; e < 8; ++e) {
            const ulonglong2 w = sW2d[k * 8 + e];
            lat2 [2*e  ] = fma2(hh, w.x, lat2 [2*e  ]);
            lat2 [2*e+1] = fma2(hh, w.y, lat2 [2*e+1]);
            dlat2[2*e  ] = fma2(hp, w.x, dlat2[2*e  ]);
            dlat2[2*e+1] = fma2(hp, w.y, dlat2[2*e+1]);
        }
    }

    // Epilogue per point (scalar): observables + relu-JVP + data + physics terms
    float err = 0.0f;
    #pragma unroll
    for (int p = 0; p < 2; ++p) {
        const int ti = base + p * 256;
        float st[16], ds[16];
        #pragma unroll
        for (int j = 0; j < 8; ++j) {
            float lo, hi; unpack2(lat2[j], lo, hi);
            st[j] = (p ? hi : lo) + sB2[j];
            unpack2(dlat2[j], lo, hi);
            ds[j] = p ? hi : lo;
        }
        #pragma unroll
        for (int j = 0; j < 8; ++j) {
            float lo, hi; unpack2(lat2[8 + j], lo, hi);
            const float q = (p ? hi : lo) + sB2[8 + j];
            const float r = q - sP[8 + j];            // q - mu
            unpack2(dlat2[8 + j], lo, hi);
            const float dl = p ? hi : lo;
            const bool pos = (r > 0.0f);              // JAX relu jvp convention
            st[8 + j] = pos ? r : 0.0f;
            ds[8 + j] = pos ? dl : 0.0f;
        }

        // Data loss terms
        #pragma unroll
        for (int j = 0; j < 16; ++j) {
            const float d = st[j] - x_target[(size_t)(b * 16 + j) * TT + ti];
            err = fmaf(d, d, err);
        }

        // Physics: da = g + Pi@x - a ; dx = (Gamma@a) * (mu - x)
        #pragma unroll
        for (int i = 0; i < 8; ++i) {
            float acc = sP[i];                        // g[i]
            #pragma unroll
            for (int j = 0; j < 8; ++j)
                acc = fmaf(sP[16 + i * 8 + j], st[8 + j], acc);
            const float da = acc - st[i];
            const float d1 = ds[i] - da;
            err = fmaf(d1, d1, err);

            float ga = 0.0f;
            #pragma unroll
            for (int j = 0; j < 8; ++j)
                ga = fmaf(sP[80 + i * 8 + j], st[j], ga);
            const float dx = ga * (sP[8 + i] - st[8 + i]);
            const float d2 = ds[8 + i] - dx;
            err = fmaf(d2, d2, err);
        }
    }

    // Supervised loss slice for this block: 18 params elems + 2 ic elems
    float sup = 0.0f;
    if (tid < 18) {
        const int i = blockIdx.x * 18 + tid;
        const float d = params_pred[i] - params_target[i];
        sup = d * d;
    } else if (tid < 20) {
        const int i = blockIdx.x * 2 + (tid - 18);
        const float d = ic_pred[i] - ic_target[i];
        sup = d * d;
    }

    // Block reduction (deterministic)
    #pragma unroll
    for (int off = 16; off; off >>= 1) {
        err += __shfl_xor_sync(0xffffffffu, err, off);
        sup += __shfl_xor_sync(0xffffffffu, sup, off);
    }
    __shared__ float sr1[TPB / 32], sr2[TPB / 32];
    if ((tid & 31) == 0) { sr1[tid >> 5] = err; sr2[tid >> 5] = sup; }
    __syncthreads();
    if (tid == 0) {
        float s = 0.0f, ss = 0.0f;
        #pragma unroll
        for (int w = 0; w < TPB / 32; ++w) { s += sr1[w]; ss += sr2[w]; }
        // data+physics divide by B*T*2N = 16777216 ; supervised by B*160 = 40960
        g_partial[blockIdx.x] = s * (1.0f / 16777216.0f) + ss * (1.0f / 40960.0f);
    }
}

__global__ __launch_bounds__(256) void pinn_finalize(float* __restrict__ out)
{
    const int tid = threadIdx.x;
    const float4* p = (const float4*)g_partial;     // NBLOCKS/4 = 512 float4
    float s = 0.0f;
    #pragma unroll
    for (int i = tid; i < NBLOCKS / 4; i += 256) {
        const float4 v = p[i];
        s += (v.x + v.y) + (v.z + v.w);
    }
    #pragma unroll
    for (int off = 16; off; off >>= 1)
        s += __shfl_xor_sync(0xffffffffu, s, off);
    __shared__ float r[8];
    if ((tid & 31) == 0) r[tid >> 5] = s;
    __syncthreads();
    if (tid == 0) {
        float a = 0.0f;
        #pragma unroll
        for (int w = 0; w < 8; ++w) a += r[w];
        out[0] = a;
    }
}

extern "C" void kernel_launch(void* const* d_in, const int* in_sizes, int n_in,
                              void* d_out, int out_size) {
    const float* t             = (const float*)d_in[0];
    const float* x_target      = (const float*)d_in[1];
    const float* params_pred   = (const float*)d_in[2];
    const float* params_target = (const float*)d_in[3];
    const float* ic_pred       = (const float*)d_in[4];
    const float* ic_target     = (const float*)d_in[5];
    const float* W1            = (const float*)d_in[6];
    const float* b1            = (const float*)d_in[7];
    const float* W2            = (const float*)d_in[8];
    const float* b2            = (const float*)d_in[9];

    pinn_point_kernel<<<NBLOCKS, TPB>>>(t, x_target, params_pred, params_target,
                                        ic_pred, ic_target, W1, b1, W2, b2);
    pinn_finalize<<<1, 256>>>((float*)d_out);
}

// round 7
// speedup vs baseline: 1.3678x; 1.2145x over previous
#include <cuda_runtime.h>

// Problem constants
#define BB 256
#define TT 4096
#define HH 64
#define TPB 256
#define CHUNKS (TT / TPB)           // 16
#define NBLOCKS (BB * CHUNKS)       // 4096

typedef unsigned long long ull;

// Deterministic reduction scratch (no atomics, no allocation)
__device__ float g_partial[NBLOCKS];

__device__ __forceinline__ ull pack2(float lo, float hi) {
    ull r; asm("mov.b64 %0, {%1, %2};" : "=l"(r) : "f"(lo), "f"(hi)); return r;
}
__device__ __forceinline__ void unpack2(ull v, float& lo, float& hi) {
    asm("mov.b64 {%0, %1}, %2;" : "=f"(lo), "=f"(hi) : "l"(v));
}
// packed 2x fp32 FMA (FFMA2) — PTX-only on sm_103a
__device__ __forceinline__ ull fma2(ull a, ull b, ull c) {
    ull d; asm("fma.rn.f32x2 %0, %1, %2, %3;" : "=l"(d) : "l"(a), "l"(b), "l"(c)); return d;
}
// hardware tanh (MUFU.TANH)
__device__ __forceinline__ float tanh_fast(float x) {
    float y; asm("tanh.approx.f32 %0, %1;" : "=f"(y) : "f"(x)); return y;
}

__global__ __launch_bounds__(TPB) void pinn_point_kernel(
    const float* __restrict__ t,
    const float* __restrict__ x_target,
    const float* __restrict__ params_pred,
    const float* __restrict__ params_target,
    const float* __restrict__ ic_pred,
    const float* __restrict__ ic_target,
    const float* __restrict__ W1,
    const float* __restrict__ b1,
    const float* __restrict__ W2,
    const float* __restrict__ b2)
{
    // W2 row k as 4x ulonglong2; each ull is a j-pair (W2[k][2e], W2[k][2e+1]).
    // W2 is row-major [64][16] so pairs are contiguous: stage as raw 16B copies.
    __shared__ ulonglong2 sW2v[HH * 4];
    __shared__ ull  sWB[HH];         // packed (W1[k], b1[k])
    __shared__ float sB2[16];
    __shared__ float sP[144];        // [0:8)=g [8:16)=mu [16:80)=Pi [80:144)=Gamma

    const int b     = blockIdx.x >> 4;            // / CHUNKS
    const int chunk = blockIdx.x & (CHUNKS - 1);
    const int tid   = threadIdx.x;

    // Stage weights + per-batch params into shared
    sW2v[tid] = ((const ulonglong2*)W2)[tid];     // HH*4 == 256 == TPB
    if (tid < HH) sWB[tid] = pack2(W1[tid], b1[tid]);
    else if (tid < HH + 16) sB2[tid - HH] = b2[tid - HH];
    if (tid >= 112) sP[tid - 112] = params_pred[b * 144 + (tid - 112)];
    __syncthreads();

    const int   ti = chunk * TPB + tid;
    const float tv = t[b * TT + ti];

    // Packed accumulators over output pairs: lat2[e] = (lat[2e], lat[2e+1])
    ull lat2[8], dlat2[8];
    #pragma unroll
    for (int e = 0; e < 8; ++e) { lat2[e] = 0ull; dlat2[e] = 0ull; }

    #pragma unroll 4
    for (int k = 0; k < HH; ++k) {
        float w1k, b1k; unpack2(sWB[k], w1k, b1k);
        const float h  = tanh_fast(fmaf(tv, w1k, b1k));
        const float hp = fmaf(-h, h, 1.0f) * w1k;
        const ull hh  = pack2(h, h);
        const ull hpp = pack2(hp, hp);
        #pragma unroll
        for (int jj = 0; jj < 4; ++jj) {
            const ulonglong2 w = sW2v[k * 4 + jj];
            lat2 [2*jj  ] = fma2(hh,  w.x, lat2 [2*jj  ]);
            lat2 [2*jj+1] = fma2(hh,  w.y, lat2 [2*jj+1]);
            dlat2[2*jj  ] = fma2(hpp, w.x, dlat2[2*jj  ]);
            dlat2[2*jj+1] = fma2(hpp, w.y, dlat2[2*jj+1]);
        }
    }

    // Unpack to scalars
    float st[16], ds[16];
    #pragma unroll
    for (int e = 0; e < 8; ++e) {
        float lo, hi;
        unpack2(lat2[e],  lo, hi); st[2*e] = lo; st[2*e+1] = hi;
        unpack2(dlat2[e], lo, hi); ds[2*e] = lo; ds[2*e+1] = hi;
    }

    // Observables + JVP through relu gate
    #pragma unroll
    for (int j = 0; j < 8; ++j) st[j] += sB2[j];
    #pragma unroll
    for (int j = 0; j < 8; ++j) {
        const float q = st[8 + j] + sB2[8 + j];
        const float r = q - sP[8 + j];                // q - mu
        const bool pos = (r > 0.0f);                  // JAX relu jvp convention
        st[8 + j] = pos ? r : 0.0f;
        ds[8 + j] = pos ? ds[8 + j] : 0.0f;
    }

    // Data loss terms
    float err = 0.0f;
    #pragma unroll
    for (int j = 0; j < 16; ++j) {
        const float d = st[j] - x_target[(size_t)(b * 16 + j) * TT + ti];
        err = fmaf(d, d, err);
    }

    // Physics: da = g + Pi@x - a ; dx = (Gamma@a) * (mu - x)
    #pragma unroll
    for (int i = 0; i < 8; ++i) {
        float acc = sP[i];                            // g[i]
        #pragma unroll
        for (int j = 0; j < 8; ++j)
            acc = fmaf(sP[16 + i * 8 + j], st[8 + j], acc);
        const float da = acc - st[i];
        const float d1 = ds[i] - da;
        err = fmaf(d1, d1, err);

        float ga = 0.0f;
        #pragma unroll
        for (int j = 0; j < 8; ++j)
            ga = fmaf(sP[80 + i * 8 + j], st[j], ga);
        const float dx = ga * (sP[8 + i] - st[8 + i]);
        const float d2 = ds[8 + i] - dx;
        err = fmaf(d2, d2, err);
    }

    // Supervised loss slice for this block: 9 params elems + 1 ic elem
    float sup = 0.0f;
    if (tid < 9) {
        const int i = blockIdx.x * 9 + tid;           // covers 4096*9 = 36864
        const float d = params_pred[i] - params_target[i];
        sup = d * d;
    } else if (tid == 9) {
        const int i = blockIdx.x;                     // covers 4096 ic elems
        const float d = ic_pred[i] - ic_target[i];
        sup = d * d;
    }

    // Block reduction (deterministic)
    #pragma unroll
    for (int off = 16; off; off >>= 1) {
        err += __shfl_xor_sync(0xffffffffu, err, off);
        sup += __shfl_xor_sync(0xffffffffu, sup, off);
    }
    __shared__ float sr1[TPB / 32], sr2[TPB / 32];
    if ((tid & 31) == 0) { sr1[tid >> 5] = err; sr2[tid >> 5] = sup; }
    __syncthreads();
    if (tid == 0) {
        float s = 0.0f, ss = 0.0f;
        #pragma unroll
        for (int w = 0; w < TPB / 32; ++w) { s += sr1[w]; ss += sr2[w]; }
        // data+physics divide by B*T*2N = 16777216 ; supervised by B*160 = 40960
        g_partial[blockIdx.x] = s * (1.0f / 16777216.0f) + ss * (1.0f / 40960.0f);
    }
}

__global__ __launch_bounds__(256) void pinn_finalize(float* __restrict__ out)
{
    const int tid = threadIdx.x;
    const float4* p = (const float4*)g_partial;      // NBLOCKS/4 = 1024 float4
    float s = 0.0f;
    #pragma unroll
    for (int i = tid; i < NBLOCKS / 4; i += 256) {
        const float4 v = p[i];
        s += (v.x + v.y) + (v.z + v.w);
    }
    #pragma unroll
    for (int off = 16; off; off >>= 1)
        s += __shfl_xor_sync(0xffffffffu, s, off);
    __shared__ float r[8];
    if ((tid & 31) == 0) r[tid >> 5] = s;
    __syncthreads();
    if (tid == 0) {
        float a = 0.0f;
        #pragma unroll
        for (int w = 0; w < 8; ++w) a += r[w];
        out[0] = a;
    }
}

extern "C" void kernel_launch(void* const* d_in, const int* in_sizes, int n_in,
                              void* d_out, int out_size) {
    const float* t             = (const float*)d_in[0];
    const float* x_target      = (const float*)d_in[1];
    const float* params_pred   = (const float*)d_in[2];
    const float* params_target = (const float*)d_in[3];
    const float* ic_pred       = (const float*)d_in[4];
    const float* ic_target     = (const float*)d_in[5];
    const float* W1            = (const float*)d_in[6];
    const float* b1            = (const float*)d_in[7];
    const float* W2            = (const float*)d_in[8];
    const float* b2            = (const float*)d_in[9];

    pinn_point_kernel<<<NBLOCKS, TPB>>>(t, x_target, params_pred, params_target,
                                        ic_pred, ic_target, W1, b1, W2, b2);
    pinn_finalize<<<1, 256>>>((float*)d_out);
}